// round 4
// baseline (speedup 1.0000x reference)
#include <cuda_runtime.h>
#include <math.h>
#include <cstdint>

// Problem constants
#define DD     768
#define BINS   385
#define CPF    770          // valid floats per transform = 2*BINS
#define CPS    784          // section stride in F/M (16B aligned)
#define NCF    2560         // padded F/M width (10*256)
#define EPITCH 1024         // padded E width
#define NTOK   16384
#define SEQ    4096
#define BATCH  4
#define KPAD   800          // padded OutF row length (25*32)

// Scratch (device globals; allocation-free per harness rules)
__device__ float g_E[DD * EPITCH];            // rDFT matrix, tf32-rounded, zero-padded
__device__ float g_Wt[3 * DD * DD];           // W^T per projection, tf32-rounded
__device__ float g_M[DD * NCF];               // Wk^T*E | Wv^T*E | Wq^T*E at CPS stride
__device__ float g_Xr[NTOK * DD];             // x rounded to tf32
__device__ float g_F[(size_t)NTOK * NCF];     // kf|vf|qf per token
__device__ float g_OutF[(size_t)NTOK * KPAD]; // mem*conj(qf), tf32-rounded
__device__ float g_G[KPAD * DD];              // inverse rDFT matrix, tf32-rounded

__device__ __forceinline__ float cvt_tf32(float x) {
    uint32_t u;
    asm("cvt.rna.tf32.f32 %0, %1;" : "=r"(u) : "f"(x));
    return __uint_as_float(u);
}
__device__ __forceinline__ float4 cvt4(float4 v) {
    float4 o;
    o.x = cvt_tf32(v.x); o.y = cvt_tf32(v.y);
    o.z = cvt_tf32(v.z); o.w = cvt_tf32(v.w);
    return o;
}

// ---------------------------------------------------------------------------
// Fill / prep kernels
// ---------------------------------------------------------------------------
__global__ void fill_E() {
    int idx = blockIdx.x * blockDim.x + threadIdx.x;
    if (idx >= DD * EPITCH) return;
    int e = idx / EPITCH, j = idx % EPITCH;
    float v = 0.f;
    if (j < CPF) {
        int m = j >> 1;
        int r = (e * m) % DD;
        float th = (float)r * (float)(2.0 * M_PI / DD);
        float s, c;
        sincosf(th, &s, &c);
        v = cvt_tf32((j & 1) ? -s : c);
    }
    g_E[idx] = v;
}

__global__ void fill_G() {
    int idx = blockIdx.x * blockDim.x + threadIdx.x;
    if (idx >= KPAD * DD) return;
    int j = idx / DD, n = idx % DD;
    float v = 0.f;
    if (j < CPF) {
        int m = j >> 1;
        float w = (m == 0 || m == BINS - 1) ? 1.f : 2.f;
        int r = (m * n) % DD;
        float th = (float)r * (float)(2.0 * M_PI / DD);
        float s, c;
        sincosf(th, &s, &c);
        v = cvt_tf32(((j & 1) ? -s : c) * (w / (float)DD));
    }
    g_G[idx] = v;
}

__global__ void zero_pad_outf() {
    int idx = blockIdx.x * blockDim.x + threadIdx.x;
    const int PADC = KPAD - CPF; // 30
    if (idx >= NTOK * PADC) return;
    int t = idx / PADC, c = CPF + idx % PADC;
    g_OutF[(size_t)t * KPAD + c] = 0.f;
}

__global__ void round_x(const float* __restrict__ x) {
    int idx = blockIdx.x * blockDim.x + threadIdx.x;
    if (idx >= NTOK * DD / 4) return;
    float4 v = reinterpret_cast<const float4*>(x)[idx];
    reinterpret_cast<float4*>(g_Xr)[idx] = cvt4(v);
}

// Transpose + round W: g_Wt[p][d][e] = tf32(W_p[e][d])
__global__ void transpose_w(const float* __restrict__ Wk,
                            const float* __restrict__ Wv,
                            const float* __restrict__ Wq) {
    __shared__ float t[32][33];
    const float* W = (blockIdx.z == 0) ? Wk : ((blockIdx.z == 1) ? Wv : Wq);
    float* T = g_Wt + (size_t)blockIdx.z * DD * DD;
    int bx = blockIdx.x * 32, by = blockIdx.y * 32;
#pragma unroll
    for (int i = 0; i < 4; i++) {
        int e = by + threadIdx.y + i * 8;
        t[threadIdx.y + i * 8][threadIdx.x] = W[(size_t)e * DD + bx + threadIdx.x];
    }
    __syncthreads();
#pragma unroll
    for (int i = 0; i < 4; i++) {
        int d = bx + threadIdx.y + i * 8;
        T[(size_t)d * DD + by + threadIdx.x] = cvt_tf32(t[threadIdx.x][threadIdx.y + i * 8]);
    }
}

// ---------------------------------------------------------------------------
// TF32 tensor GEMM: C = A[M,K] * B[K,N], row-major, 128x256 tile, BK=32,
// 4-stage cp.async, 256 threads (8 warps, 2x4, warp tile 64x64).
// Inputs must be pre-rounded to tf32 (mma.sync truncation then exact).
// MODE 0: plain store. MODE 1: C = X + gain*acc. MODE 2 (precompute):
//   A += z*astride, C col offset z*CPS, store only col<nvalid, rna-round.
// ---------------------------------------------------------------------------
#define GBM 128
#define GBN 256
#define GBK 32
#define APD 36
#define BPD 264
#define ASZ (GBM * APD)      // 4608 floats
#define BSZ (GBK * BPD)      // 8448 floats
#define NST 4
#define SMEMB ((ASZ + BSZ) * NST * 4)   // 208896 B

__device__ __forceinline__ void cpa16(uint32_t dst, const void* src) {
    asm volatile("cp.async.cg.shared.global [%0], [%1], 16;\n" :: "r"(dst), "l"(src));
}
__device__ __forceinline__ void cpcommit() { asm volatile("cp.async.commit_group;\n"); }
template <int N>
__device__ __forceinline__ void cpwait() { asm volatile("cp.async.wait_group %0;\n" :: "n"(N)); }

__device__ __forceinline__ void ldsm4(uint32_t* r, uint32_t addr) {
    asm volatile("ldmatrix.sync.aligned.m8n8.x4.shared.b16 {%0,%1,%2,%3}, [%4];\n"
        : "=r"(r[0]), "=r"(r[1]), "=r"(r[2]), "=r"(r[3]) : "r"(addr));
}
__device__ __forceinline__ void mma_tf32(float* d, const uint32_t* a, const uint32_t* b) {
    asm volatile(
        "mma.sync.aligned.m16n8k8.row.col.f32.tf32.tf32.f32 "
        "{%0,%1,%2,%3}, {%4,%5,%6,%7}, {%8,%9}, {%0,%1,%2,%3};\n"
        : "+f"(d[0]), "+f"(d[1]), "+f"(d[2]), "+f"(d[3])
        : "r"(a[0]), "r"(a[1]), "r"(a[2]), "r"(a[3]), "r"(b[0]), "r"(b[1]));
}

template <int MODE>
__global__ __launch_bounds__(256) void gemm_tc(
    int K,
    const float* __restrict__ A, int lda,
    const float* __restrict__ B, int ldb,
    float* __restrict__ C, int ldc,
    const float* __restrict__ X, const float* __restrict__ gainp,
    int astride, int nvalid)
{
    extern __shared__ float sm[];
    float* smA = sm;                 // [NST][ASZ]
    float* smB = sm + NST * ASZ;     // [NST][BSZ]

    const int tid = threadIdx.x;
    const int lane = tid & 31;
    const int wid = tid >> 5;
    const int wm = (wid >> 2) * 64;
    const int wn = (wid & 3) * 64;
    const int bm0 = blockIdx.y * GBM;
    const int bn0 = blockIdx.x * GBN;

    const float* Ab = A;
    int coff = 0;
    if (MODE == 2) { Ab = A + (size_t)blockIdx.z * astride; coff = blockIdx.z * CPS; }

    // cp.async staging mapping
    const int arow = tid >> 1;            // 0..127
    const int acb  = (tid & 1) * 4;       // 0 or 4 (chunks step +8)
    const int brow = tid >> 3;            // 0..31
    const int bcb  = (tid & 7) * 4;       // 0..28 (chunks step +32)
    const float* Aptr = Ab + (size_t)(bm0 + arow) * lda + acb;
    const float* Bptr = B + (size_t)brow * ldb + bn0 + bcb;
    const uint32_t sA = (uint32_t)__cvta_generic_to_shared(smA);
    const uint32_t sB = (uint32_t)__cvta_generic_to_shared(smB);
    const uint32_t dA = sA + (uint32_t)(arow * APD + acb) * 4;
    const uint32_t dB = sB + (uint32_t)(brow * BPD + bcb) * 4;

    const int KT = K / GBK;

    // prologue: stages 0..NST-2
#pragma unroll
    for (int s = 0; s < NST - 1; s++) {
        size_t ko = (size_t)s * GBK;
#pragma unroll
        for (int r = 0; r < 4; r++)
            cpa16(dA + (uint32_t)(s * ASZ + r * 8) * 4, Aptr + ko + r * 8);
#pragma unroll
        for (int r = 0; r < 8; r++)
            cpa16(dB + (uint32_t)(s * BSZ + r * 32) * 4, Bptr + ko * ldb + r * 32);
        cpcommit();
    }

    // fragment addressing
    const int rin = lane & 7;
    const int sel = lane >> 3;
    const int aoff = (wm + (sel & 1) * 8 + rin) * APD + (sel >> 1) * 4;
    const int bkf = lane & 3;
    const int bnf = wn + (lane >> 2);

    float acc[4][8][4];
#pragma unroll
    for (int mf = 0; mf < 4; mf++)
#pragma unroll
        for (int nf = 0; nf < 8; nf++)
#pragma unroll
            for (int q = 0; q < 4; q++) acc[mf][nf][q] = 0.f;

    int st = 0;
    for (int kt = 0; kt < KT; kt++) {
        cpwait<NST - 2>();
        __syncthreads();
        // issue tile kt+NST-1 into the stage freed at iter kt-1
        if (kt + NST - 1 < KT) {
            int s = (kt + NST - 1) & (NST - 1);
            size_t ko = (size_t)(kt + NST - 1) * GBK;
#pragma unroll
            for (int r = 0; r < 4; r++)
                cpa16(dA + (uint32_t)(s * ASZ + r * 8) * 4, Aptr + ko + r * 8);
#pragma unroll
            for (int r = 0; r < 8; r++)
                cpa16(dB + (uint32_t)(s * BSZ + r * 32) * 4, Bptr + ko * ldb + r * 32);
        }
        cpcommit();

        const uint32_t aBase = sA + (uint32_t)(st * ASZ) * 4;
        const float* pb = smB + st * BSZ;
#pragma unroll
        for (int ks = 0; ks < 4; ks++) {
            uint32_t a[4][4];
#pragma unroll
            for (int mf = 0; mf < 4; mf++)
                ldsm4(a[mf], aBase + (uint32_t)(aoff + mf * 16 * APD + ks * 8) * 4);
            uint32_t b[8][2];
#pragma unroll
            for (int nf = 0; nf < 8; nf++) {
                b[nf][0] = __float_as_uint(pb[(ks * 8 + bkf) * BPD + bnf + nf * 8]);
                b[nf][1] = __float_as_uint(pb[(ks * 8 + bkf + 4) * BPD + bnf + nf * 8]);
            }
#pragma unroll
            for (int mf = 0; mf < 4; mf++)
#pragma unroll
                for (int nf = 0; nf < 8; nf++)
                    mma_tf32(acc[mf][nf], a[mf], b[nf]);
        }
        st = (st + 1) & (NST - 1);
    }

    // epilogue
    float g = (MODE == 1) ? gainp[0] : 0.f;
#pragma unroll
    for (int mf = 0; mf < 4; mf++) {
        int row = bm0 + wm + mf * 16 + (lane >> 2);
#pragma unroll
        for (int nf = 0; nf < 8; nf++) {
            int col = bn0 + wn + nf * 8 + (lane & 3) * 2;
            size_t i0 = (size_t)row * ldc + coff + col;
            size_t i1 = i0 + (size_t)8 * ldc;
            if (MODE == 2) {
                if (col < nvalid) {
                    float2 o0 = make_float2(cvt_tf32(acc[mf][nf][0]), cvt_tf32(acc[mf][nf][1]));
                    float2 o1 = make_float2(cvt_tf32(acc[mf][nf][2]), cvt_tf32(acc[mf][nf][3]));
                    *reinterpret_cast<float2*>(C + i0) = o0;
                    *reinterpret_cast<float2*>(C + i1) = o1;
                }
            } else if (MODE == 1) {
                float2 x0 = *reinterpret_cast<const float2*>(X + i0);
                float2 x1 = *reinterpret_cast<const float2*>(X + i1);
                float2 o0 = make_float2(x0.x + g * acc[mf][nf][0], x0.y + g * acc[mf][nf][1]);
                float2 o1 = make_float2(x1.x + g * acc[mf][nf][2], x1.y + g * acc[mf][nf][3]);
                *reinterpret_cast<float2*>(C + i0) = o0;
                *reinterpret_cast<float2*>(C + i1) = o1;
            } else {
                *reinterpret_cast<float2*>(C + i0) =
                    make_float2(acc[mf][nf][0], acc[mf][nf][1]);
                *reinterpret_cast<float2*>(C + i1) =
                    make_float2(acc[mf][nf][2], acc[mf][nf][3]);
            }
        }
    }
}

// ---------------------------------------------------------------------------
// Causal complex cumsum of kf*vf per (batch, bin), times conj(qf).
// 2 bins/thread via float4 (sections CPS-aligned). Output rna-rounded.
// grid (BATCH, 25), block (8, 32).
// ---------------------------------------------------------------------------
__global__ void scan_kernel() {
    int b = blockIdx.x, mg = blockIdx.y;
    int j = threadIdx.x, l = threadIdx.y;
    int m0 = mg * 16 + 2 * j;
    bool a0 = m0 < BINS, a1 = (m0 + 1) < BINS;
    const int CH = SEQ / 32;   // 128
    int sbase = b * SEQ + l * CH;
    int km = 2 * m0;

    float s0r = 0.f, s0i = 0.f, s1r = 0.f, s1i = 0.f;
    const float* bp = g_F + (size_t)sbase * NCF + km;
    if (a1) {
#pragma unroll 4
        for (int i = 0; i < CH; i++) {
            const float* row = bp + (size_t)i * NCF;
            float4 k4 = *reinterpret_cast<const float4*>(row);
            float4 v4 = *reinterpret_cast<const float4*>(row + CPS);
            s0r += k4.x * v4.x - k4.y * v4.y;
            s0i += k4.x * v4.y + k4.y * v4.x;
            s1r += k4.z * v4.z - k4.w * v4.w;
            s1i += k4.z * v4.w + k4.w * v4.z;
        }
    } else if (a0) {
        for (int i = 0; i < CH; i++) {
            const float* row = bp + (size_t)i * NCF;
            float2 k2 = *reinterpret_cast<const float2*>(row);
            float2 v2 = *reinterpret_cast<const float2*>(row + CPS);
            s0r += k2.x * v2.x - k2.y * v2.y;
            s0i += k2.x * v2.y + k2.y * v2.x;
        }
    }
    __shared__ float p0r[8][33], p0i[8][33], p1r[8][33], p1i[8][33];
    p0r[j][l] = s0r; p0i[j][l] = s0i; p1r[j][l] = s1r; p1i[j][l] = s1i;
    __syncthreads();
    if (l == 0) {
        float a = 0.f, c = 0.f, d = 0.f, e = 0.f;
        for (int q = 0; q < 32; q++) {
            float t0 = p0r[j][q], t1 = p0i[j][q], t2 = p1r[j][q], t3 = p1i[j][q];
            p0r[j][q] = a; p0i[j][q] = c; p1r[j][q] = d; p1i[j][q] = e;
            a += t0; c += t1; d += t2; e += t3;
        }
    }
    __syncthreads();
    float m0r = p0r[j][l], m0i = p0i[j][l], m1r = p1r[j][l], m1i = p1i[j][l];
    float* op = g_OutF + (size_t)sbase * KPAD + km;
    if (a1) {
#pragma unroll 2
        for (int i = 0; i < CH; i++) {
            const float* row = bp + (size_t)i * NCF;
            float4 k4 = *reinterpret_cast<const float4*>(row);
            float4 v4 = *reinterpret_cast<const float4*>(row + CPS);
            float4 q4 = *reinterpret_cast<const float4*>(row + 2 * CPS);
            m0r += k4.x * v4.x - k4.y * v4.y;
            m0i += k4.x * v4.y + k4.y * v4.x;
            m1r += k4.z * v4.z - k4.w * v4.w;
            m1i += k4.z * v4.w + k4.w * v4.z;
            float4 o;
            o.x = cvt_tf32(m0r * q4.x + m0i * q4.y);
            o.y = cvt_tf32(m0i * q4.x - m0r * q4.y);
            o.z = cvt_tf32(m1r * q4.z + m1i * q4.w);
            o.w = cvt_tf32(m1i * q4.z - m1r * q4.w);
            *reinterpret_cast<float4*>(op + (size_t)i * KPAD) = o;
        }
    } else if (a0) {
        for (int i = 0; i < CH; i++) {
            const float* row = bp + (size_t)i * NCF;
            float2 k2 = *reinterpret_cast<const float2*>(row);
            float2 v2 = *reinterpret_cast<const float2*>(row + CPS);
            float2 q2 = *reinterpret_cast<const float2*>(row + 2 * CPS);
            m0r += k2.x * v2.x - k2.y * v2.y;
            m0i += k2.x * v2.y + k2.y * v2.x;
            float2 o;
            o.x = cvt_tf32(m0r * q2.x + m0i * q2.y);
            o.y = cvt_tf32(m0i * q2.x - m0r * q2.y);
            *reinterpret_cast<float2*>(op + (size_t)i * KPAD) = o;
        }
    }
}

// ---------------------------------------------------------------------------
// Launch
// ---------------------------------------------------------------------------
extern "C" void kernel_launch(void* const* d_in, const int* in_sizes, int n_in,
                              void* d_out, int out_size) {
    const float* x    = (const float*)d_in[0];
    const float* Wk   = (const float*)d_in[1];
    const float* Wv   = (const float*)d_in[2];
    const float* Wq   = (const float*)d_in[3];
    const float* gain = (const float*)d_in[4];
    float* out = (float*)d_out;

    float *pE, *pWt, *pM, *pXr, *pF, *pO, *pG;
    cudaGetSymbolAddress((void**)&pE,  g_E);
    cudaGetSymbolAddress((void**)&pWt, g_Wt);
    cudaGetSymbolAddress((void**)&pM,  g_M);
    cudaGetSymbolAddress((void**)&pXr, g_Xr);
    cudaGetSymbolAddress((void**)&pF,  g_F);
    cudaGetSymbolAddress((void**)&pO,  g_OutF);
    cudaGetSymbolAddress((void**)&pG,  g_G);

    cudaFuncSetAttribute(gemm_tc<0>, cudaFuncAttributeMaxDynamicSharedMemorySize, SMEMB);
    cudaFuncSetAttribute(gemm_tc<1>, cudaFuncAttributeMaxDynamicSharedMemorySize, SMEMB);
    cudaFuncSetAttribute(gemm_tc<2>, cudaFuncAttributeMaxDynamicSharedMemorySize, SMEMB);

    transpose_w<<<dim3(DD / 32, DD / 32, 3), dim3(32, 8)>>>(Wk, Wv, Wq);
    fill_E<<<(DD * EPITCH + 255) / 256, 256>>>();
    fill_G<<<(KPAD * DD + 255) / 256, 256>>>();
    zero_pad_outf<<<(NTOK * (KPAD - CPF) + 255) / 256, 256>>>();
    round_x<<<(NTOK * DD / 4 + 255) / 256, 256>>>(x);

    // Precompute: M_p = Wt_p @ E (tf32 tensor, guarded+rounded store)
    gemm_tc<2><<<dim3(EPITCH / GBN, DD / GBM, 3), 256, SMEMB>>>(
        DD, pWt, DD, pE, EPITCH, pM, NCF, nullptr, nullptr, DD * DD, CPF);

    // Forward: F = Xr @ M
    gemm_tc<0><<<dim3(NCF / GBN, NTOK / GBM), 256, SMEMB>>>(
        DD, pXr, DD, pM, NCF, pF, NCF, nullptr, nullptr, 0, 0);

    // Causal binding scan
    scan_kernel<<<dim3(BATCH, 25), dim3(8, 32)>>>();

    // Inverse: out = x + gain * (OutF @ G)
    gemm_tc<1><<<dim3(DD / GBN, NTOK / GBM), 256, SMEMB>>>(
        KPAD, pO, KPAD, pG, DD, out, DD, x, gain, 0, 0);
}